// round 5
// baseline (speedup 1.0000x reference)
#include <cuda_runtime.h>
#include <cstdint>
#include <math_constants.h>

#define WINS   4096
#define NTOK   49
#define DIM    256
#define HEADS  8
#define DH     32
#define TTOT   (WINS * NTOK)      // 200704
#define QKV_E  (3 * DIM)          // 768
#define SCALE  0.17677669529663687f

// ------------------------- scratch (device globals) -------------------------
__device__ float g_qkv[(size_t)TTOT * QKV_E];   // ~616 MB
__device__ float g_att[(size_t)TTOT * DIM];     // ~205 MB
__device__ float g_bias[HEADS * NTOK * NTOK];

// ------------------------------ helpers ------------------------------------
__device__ __forceinline__ float tf32r(float x) {
    float r; asm("cvt.rna.tf32.f32 %0, %1;" : "=f"(r) : "f"(x)); return r;
}
__device__ __forceinline__ unsigned long long pack2(float lo, float hi) {
    unsigned long long r;
    asm("mov.b64 %0, {%1, %2};" : "=l"(r) : "f"(lo), "f"(hi));
    return r;
}
__device__ __forceinline__ void unpack2(unsigned long long v, float& lo, float& hi) {
    asm("mov.b64 {%0, %1}, %2;" : "=f"(lo), "=f"(hi) : "l"(v));
}
#define FMA2(d, a, b, c) \
    asm("fma.rn.f32x2 %0, %1, %2, %3;" : "=l"(d) : "l"(a), "l"(b), "l"(c))
__device__ __forceinline__ float hadd2(unsigned long long v) {
    float lo, hi; unpack2(v, lo, hi); return lo + hi;
}
__device__ __forceinline__ void mma_tf32(float* d, const uint32_t* a, const uint32_t* b) {
    asm volatile(
        "mma.sync.aligned.m16n8k8.row.col.f32.tf32.tf32.f32 "
        "{%0,%1,%2,%3}, {%4,%5,%6,%7}, {%8,%9}, {%0,%1,%2,%3};"
        : "+f"(d[0]), "+f"(d[1]), "+f"(d[2]), "+f"(d[3])
        : "r"(a[0]), "r"(a[1]), "r"(a[2]), "r"(a[3]), "r"(b[0]), "r"(b[1]));
}

// ------------------------------ GEMM (tf32 mma.sync) ------------------------
// C[M,N] = A[M,K] @ B[N,K]^T.  CTA tile 128x256, BK=16, 256 threads (8 warps,
// 2x4 grid, each warp 64x64). Register-staged global loads with tf32 rounding
// fused into STS; double-buffered smem; ONE barrier per K-step.
#define BM 128
#define BN 256
#define BK 16
#define KSTR 20                          // padded floats per row
#define A_ST (BM * KSTR)                 // 2560 floats per stage
#define B_ST (BN * KSTR)                 // 5120 floats per stage
#define SMEM_DYN (2 * (A_ST + B_ST) * 4) // 61440 bytes

__global__ void __launch_bounds__(256, 1) gemm_tf32_kernel(
    const float* __restrict__ A, const float* __restrict__ B,
    float* __restrict__ C, int M, int N, int K)
{
    extern __shared__ float smem[];
    float* sA = smem;                    // [2][BM][KSTR]
    float* sB = smem + 2 * A_ST;         // [2][BN][KSTR]

    const int tid  = threadIdx.x;
    const int lane = tid & 31;
    const int wid  = tid >> 5;
    const int wm   = wid & 1;            // 0..1  (64-row slabs)
    const int wn   = wid >> 1;           // 0..3  (64-col slabs)
    const int r    = lane >> 2;          // groupID 0..7
    const int c    = lane & 3;           // threadID_in_group 0..3
    const int bm   = blockIdx.y * BM;
    const int bn   = blockIdx.x * BN;
    const int KSTEPS = K / BK;

    float acc[4][8][4];
#pragma unroll
    for (int mt = 0; mt < 4; mt++)
#pragma unroll
        for (int nt = 0; nt < 8; nt++)
#pragma unroll
            for (int i = 0; i < 4; i++) acc[mt][nt][i] = 0.f;

    // staging registers: A 2 float4, B 4 float4
    float4 rgA[2], rgB[4];
    const int ld_row = tid >> 2;         // 0..63
    const int ld_c4  = tid & 3;          // float4 index within BK=16

    auto loadG = [&](int ks) {
        const int k0 = ks * BK;
#pragma unroll
        for (int rr = 0; rr < 2; rr++)
            rgA[rr] = *(const float4*)&A[(size_t)(bm + ld_row + rr * 64) * K + k0 + ld_c4 * 4];
#pragma unroll
        for (int rr = 0; rr < 4; rr++)
            rgB[rr] = *(const float4*)&B[(size_t)(bn + ld_row + rr * 64) * K + k0 + ld_c4 * 4];
    };
    auto stsStage = [&](int st) {
        float* dA = sA + st * A_ST;
        float* dB = sB + st * B_ST;
#pragma unroll
        for (int rr = 0; rr < 2; rr++) {
            float4 v = rgA[rr];
            v.x = tf32r(v.x); v.y = tf32r(v.y); v.z = tf32r(v.z); v.w = tf32r(v.w);
            *(float4*)&dA[(ld_row + rr * 64) * KSTR + ld_c4 * 4] = v;
        }
#pragma unroll
        for (int rr = 0; rr < 4; rr++) {
            float4 v = rgB[rr];
            v.x = tf32r(v.x); v.y = tf32r(v.y); v.z = tf32r(v.z); v.w = tf32r(v.w);
            *(float4*)&dB[(ld_row + rr * 64) * KSTR + ld_c4 * 4] = v;
        }
    };

    loadG(0);
    stsStage(0);
    __syncthreads();

    for (int ks = 0; ks < KSTEPS; ks++) {
        const int cur = ks & 1;
        if (ks + 1 < KSTEPS) loadG(ks + 1);

        const float* Acur = sA + cur * A_ST + (wm * 64 + r) * KSTR + c;
        const float* Bcur = sB + cur * B_ST + (wn * 64 + r) * KSTR + c;
#pragma unroll
        for (int k8 = 0; k8 < 2; k8++) {
            const int kb = k8 * 8;
            uint32_t af[4][4], bf[8][2];
#pragma unroll
            for (int mt = 0; mt < 4; mt++) {
                const float* p = Acur + mt * 16 * KSTR + kb;
                af[mt][0] = __float_as_uint(p[0]);
                af[mt][1] = __float_as_uint(p[8 * KSTR]);
                af[mt][2] = __float_as_uint(p[4]);
                af[mt][3] = __float_as_uint(p[8 * KSTR + 4]);
            }
#pragma unroll
            for (int nt = 0; nt < 8; nt++) {
                const float* p = Bcur + nt * 8 * KSTR + kb;
                bf[nt][0] = __float_as_uint(p[0]);
                bf[nt][1] = __float_as_uint(p[4]);
            }
#pragma unroll
            for (int mt = 0; mt < 4; mt++)
#pragma unroll
                for (int nt = 0; nt < 8; nt++)
                    mma_tf32(acc[mt][nt], af[mt], bf[nt]);
        }

        if (ks + 1 < KSTEPS) {
            stsStage((ks + 1) & 1);      // writes the OTHER buffer: no hazard
            __syncthreads();             // single barrier per step
        }
    }

    // epilogue
#pragma unroll
    for (int mt = 0; mt < 4; mt++) {
        const int row = bm + wm * 64 + mt * 16 + r;
#pragma unroll
        for (int nt = 0; nt < 8; nt++) {
            const int col = bn + wn * 64 + nt * 8 + 2 * c;
            *(float2*)&C[(size_t)row * N + col] =
                make_float2(acc[mt][nt][0], acc[mt][nt][1]);
            *(float2*)&C[(size_t)(row + 8) * N + col] =
                make_float2(acc[mt][nt][2], acc[mt][nt][3]);
        }
    }
}

// --------------------------- attention (fp32) -------------------------------
// One block = one (window, head). Thread i owns query row i; k/v reads are
// warp-broadcast from SMEM; packed fma.rn.f32x2 with 4 accumulator chains.
__global__ void __launch_bounds__(64) attn_kernel(
    const float* __restrict__ qkv, const float* __restrict__ biasmat,
    float* __restrict__ out)
{
    __shared__ float ks[NTOK][DH];
    __shared__ float vs[NTOK][DH];
    __shared__ float sims[NTOK][50];

    const int win = blockIdx.x, head = blockIdx.y, tid = threadIdx.x;
    const size_t wbase = (size_t)win * NTOK * QKV_E + head * DH;

    // bias pre-staged into sims
    for (int e = tid; e < NTOK * NTOK; e += 64) {
        int i = e / NTOK, j = e - i * NTOK;
        sims[i][j] = biasmat[head * (NTOK * NTOK) + e];
    }
    // k, v tiles
    for (int u = tid; u < NTOK * 8; u += 64) {
        int j = u >> 3, c4 = u & 7;
        const float* p = qkv + wbase + (size_t)j * QKV_E;
        *(float4*)&ks[j][c4 * 4] = *(const float4*)(p + DIM + c4 * 4);
        *(float4*)&vs[j][c4 * 4] = *(const float4*)(p + 2 * DIM + c4 * 4);
    }
    // q row in registers, scale folded in
    unsigned long long q2[16];
    const int i = tid;
    if (i < NTOK) {
        const float* qp = qkv + wbase + (size_t)i * QKV_E;
#pragma unroll
        for (int c4 = 0; c4 < 8; c4++) {
            float4 v = *(const float4*)(qp + c4 * 4);
            q2[2 * c4]     = pack2(v.x * SCALE, v.y * SCALE);
            q2[2 * c4 + 1] = pack2(v.z * SCALE, v.w * SCALE);
        }
    }
    __syncthreads();

    if (i < NTOK) {
        float m = -CUDART_INF_F;
        for (int j = 0; j < NTOK; j++) {
            unsigned long long a0 = 0ull, a1 = 0ull, a2 = 0ull, a3 = 0ull;
            const unsigned long long* kr = (const unsigned long long*)ks[j];
#pragma unroll
            for (int cc = 0; cc < 16; cc += 4) {
                FMA2(a0, q2[cc],     kr[cc],     a0);
                FMA2(a1, q2[cc + 1], kr[cc + 1], a1);
                FMA2(a2, q2[cc + 2], kr[cc + 2], a2);
                FMA2(a3, q2[cc + 3], kr[cc + 3], a3);
            }
            float s = (hadd2(a0) + hadd2(a1)) + (hadd2(a2) + hadd2(a3)) + sims[i][j];
            sims[i][j] = s;
            m = fmaxf(m, s);
        }
        float sum = 0.f;
        for (int j = 0; j < NTOK; j++) {
            float e = __expf(sims[i][j] - m);
            sims[i][j] = e; sum += e;
        }
        float inv = 1.f / sum;

        unsigned long long o2[16];
#pragma unroll
        for (int cc = 0; cc < 16; cc++) o2[cc] = 0ull;
        for (int j = 0; j < NTOK; j++) {
            float p = sims[i][j];
            unsigned long long pp = pack2(p, p);
            const unsigned long long* vr = (const unsigned long long*)vs[j];
#pragma unroll
            for (int cc = 0; cc < 16; cc++) FMA2(o2[cc], pp, vr[cc], o2[cc]);
        }
        float* orow = out + ((size_t)win * NTOK + i) * DIM + head * DH;
#pragma unroll
        for (int cc = 0; cc < 16; cc += 2) {
            float a, b, x, y;
            unpack2(o2[cc], a, b); unpack2(o2[cc + 1], x, y);
            *(float4*)(orow + cc * 2) = make_float4(a * inv, b * inv, x * inv, y * inv);
        }
    }
}

// ------------------------------ bias expand ---------------------------------
__global__ void bias_expand_kernel(const float* __restrict__ rel_emb,
                                   const int* __restrict__ rel_idx,
                                   float* __restrict__ biasmat)
{
    int e = blockIdx.x * 256 + threadIdx.x;
    if (e < HEADS * NTOK * NTOK) {
        int h = e / (NTOK * NTOK);
        int t = e - h * (NTOK * NTOK);
        biasmat[e] = rel_emb[rel_idx[t] * HEADS + h];
    }
}

// ----------------------------------------------------------------------------
extern "C" void kernel_launch(void* const* d_in, const int* in_sizes, int n_in,
                              void* d_out, int out_size)
{
    const float* x       = (const float*)d_in[0];
    const float* w_qkv   = (const float*)d_in[1];
    const float* w_out   = (const float*)d_in[2];
    const float* rel_emb = (const float*)d_in[3];
    const int*   rel_idx = (const int*)d_in[4];
    float* out = (float*)d_out;

    float *qkv, *att, *bias;
    cudaGetSymbolAddress((void**)&qkv,  g_qkv);
    cudaGetSymbolAddress((void**)&att,  g_att);
    cudaGetSymbolAddress((void**)&bias, g_bias);

    cudaFuncSetAttribute(gemm_tf32_kernel,
                         cudaFuncAttributeMaxDynamicSharedMemorySize, SMEM_DYN);

    bias_expand_kernel<<<(HEADS * NTOK * NTOK + 255) / 256, 256>>>(rel_emb, rel_idx, bias);

    // 1) qkv = x @ w_qkv^T   (tf32 tensor cores via mma.sync)
    gemm_tf32_kernel<<<dim3(QKV_E / BN, TTOT / BM), 256, SMEM_DYN>>>(
        x, w_qkv, qkv, TTOT, QKV_E, DIM);

    // 2) windowed attention
    attn_kernel<<<dim3(WINS, HEADS), 64>>>(qkv, bias, att);

    // 3) out = att @ w_out^T
    gemm_tf32_kernel<<<dim3(DIM / BN, TTOT / BM), 256, SMEM_DYN>>>(
        att, w_out, out, TTOT, DIM, DIM);
}

// round 6
// speedup vs baseline: 2.1113x; 2.1113x over previous
#include <cuda_runtime.h>
#include <cuda_fp16.h>
#include <cstdint>

#define WINS   4096
#define NTOK   49
#define DIM    256
#define HEADS  8
#define DH     32
#define TTOT   (WINS * NTOK)      // 200704
#define QKV_E  768
#define SCALE  0.17677669529663687f

// ------------------------- scratch (device globals) -------------------------
__device__ __half g_x16 [(size_t)TTOT * DIM];     // 103 MB
__device__ __half g_wq16[QKV_E * DIM];
__device__ __half g_wo16[DIM * DIM];
__device__ __half g_qkv [(size_t)TTOT * QKV_E];   // 308 MB
__device__ __half g_att [(size_t)TTOT * DIM];     // 103 MB
__device__ float  g_biasP[HEADS * 64 * 64];       // padded bias, -1e9 outside 49x49

// ------------------------------ helpers ------------------------------------
__device__ __forceinline__ uint32_t smem_u32(const void* p) {
    uint32_t a;
    asm("{ .reg .u64 t; cvta.to.shared.u64 t, %1; cvt.u32.u64 %0, t; }"
        : "=r"(a) : "l"(p));
    return a;
}
__device__ __forceinline__ void cp16(uint32_t dst, const void* src) {
    asm volatile("cp.async.ca.shared.global [%0], [%1], 16;\n" :: "r"(dst), "l"(src));
}
__device__ __forceinline__ void cp_commit() {
    asm volatile("cp.async.commit_group;\n" ::);
}
template <int N> __device__ __forceinline__ void cp_wait() {
    asm volatile("cp.async.wait_group %0;\n" :: "n"(N) : "memory");
}
__device__ __forceinline__ void ldsm4(uint32_t& r0, uint32_t& r1, uint32_t& r2,
                                      uint32_t& r3, uint32_t a) {
    asm volatile("ldmatrix.sync.aligned.m8n8.x4.shared.b16 {%0,%1,%2,%3}, [%4];"
                 : "=r"(r0), "=r"(r1), "=r"(r2), "=r"(r3) : "r"(a) : "memory");
}
__device__ __forceinline__ void ldsm4t(uint32_t& r0, uint32_t& r1, uint32_t& r2,
                                       uint32_t& r3, uint32_t a) {
    asm volatile("ldmatrix.sync.aligned.m8n8.x4.trans.shared.b16 {%0,%1,%2,%3}, [%4];"
                 : "=r"(r0), "=r"(r1), "=r"(r2), "=r"(r3) : "r"(a) : "memory");
}
__device__ __forceinline__ void mma16816(float* d, uint32_t a0, uint32_t a1,
                                         uint32_t a2, uint32_t a3,
                                         uint32_t b0, uint32_t b1) {
    asm volatile(
        "mma.sync.aligned.m16n8k16.row.col.f32.f16.f16.f32 "
        "{%0,%1,%2,%3}, {%4,%5,%6,%7}, {%8,%9}, {%0,%1,%2,%3};"
        : "+f"(d[0]), "+f"(d[1]), "+f"(d[2]), "+f"(d[3])
        : "r"(a0), "r"(a1), "r"(a2), "r"(a3), "r"(b0), "r"(b1));
}
__device__ __forceinline__ uint32_t f22h2(float lo, float hi) {
    uint32_t r;
    asm("cvt.rn.f16x2.f32 %0, %1, %2;" : "=r"(r) : "f"(hi), "f"(lo));
    return r;
}

// ------------------------------ GEMM (fp16 mma) ------------------------------
// C[M,N] = A[M,K]@B[N,K]^T, A/B fp16. CTA 128x128, BK=32, 256 thr (8 warps 2x4,
// warp 64x32). 3-stage cp.async pipeline; ldmatrix fragments.
// Smem row = 32 fp16 (64B) padded to 80B for bank-spread.
#define GROW 80                     // bytes per smem row
#define STAGE_B 20480               // (128 + 128) rows * 80B
#define GSMEM (3 * STAGE_B)         // 61440

template <int HALF_OUT>
__global__ void __launch_bounds__(256, 2) gemm_h_kernel(
    const __half* __restrict__ A, const __half* __restrict__ B,
    void* __restrict__ Cv, int M, int N, int K)
{
    extern __shared__ char smem[];
    const uint32_t sbase = smem_u32(smem);

    const int tid = threadIdx.x, lane = tid & 31, wid = tid >> 5;
    const int wm = wid & 1, wn = wid >> 1;
    const int bm = blockIdx.y * 128, bn = blockIdx.x * 128;
    const int KSTEPS = K >> 5;

    // cp.async mapping: 4 chunks/thread/stage (A 512 + B 512 chunks)
    const int c_row = tid >> 2;          // 0..63
    const int c_ch  = tid & 3;
    auto ld_stage = [&](int ks, int buf) {
        const uint32_t sa = sbase + buf * STAGE_B;
        const int k0 = ks * 32;
#pragma unroll
        for (int h = 0; h < 2; h++) {    // A rows c_row, c_row+64
            cp16(sa + (c_row + h * 64) * GROW + c_ch * 16,
                 A + (size_t)(bm + c_row + h * 64) * K + k0 + c_ch * 8);
            cp16(sa + 10240 + (c_row + h * 64) * GROW + c_ch * 16,
                 B + (size_t)(bn + c_row + h * 64) * K + k0 + c_ch * 8);
        }
        cp_commit();
    };

    float acc[4][4][4];
#pragma unroll
    for (int mt = 0; mt < 4; mt++)
#pragma unroll
        for (int nt = 0; nt < 4; nt++)
#pragma unroll
            for (int i = 0; i < 4; i++) acc[mt][nt][i] = 0.f;

    // ldmatrix lane addressing
    const int l7 = lane & 7;
    const uint32_t aOff = (uint32_t)((wm * 64 + l7 + ((lane >> 3) & 1) * 8) * GROW
                                     + (lane >> 4) * 16);
    const uint32_t bOff = (uint32_t)(10240 + (wn * 32 + (lane >> 4) * 8 + l7) * GROW
                                     + ((lane >> 3) & 1) * 16);

    ld_stage(0, 0);
    ld_stage(1, 1);

    for (int ks = 0; ks < KSTEPS; ks++) {
        if (ks == KSTEPS - 1) cp_wait<0>(); else cp_wait<1>();
        __syncthreads();
        const uint32_t sa = sbase + (ks % 3) * STAGE_B;

#pragma unroll
        for (int kt = 0; kt < 2; kt++) {
            uint32_t af[4][4], bf[4][2];
#pragma unroll
            for (int mt = 0; mt < 4; mt++)
                ldsm4(af[mt][0], af[mt][1], af[mt][2], af[mt][3],
                      sa + aOff + mt * 16 * GROW + kt * 32);
#pragma unroll
            for (int p = 0; p < 2; p++)
                ldsm4(bf[2 * p][0], bf[2 * p][1], bf[2 * p + 1][0], bf[2 * p + 1][1],
                      sa + bOff + p * 16 * GROW + kt * 32);
#pragma unroll
            for (int mt = 0; mt < 4; mt++)
#pragma unroll
                for (int nt = 0; nt < 4; nt++)
                    mma16816(acc[mt][nt], af[mt][0], af[mt][1], af[mt][2], af[mt][3],
                             bf[nt][0], bf[nt][1]);
        }
        if (ks + 2 < KSTEPS) ld_stage(ks + 2, (ks + 2) % 3);
    }

    // epilogue
    const int r = lane >> 2, c = lane & 3;
#pragma unroll
    for (int mt = 0; mt < 4; mt++) {
        const int row = bm + wm * 64 + mt * 16 + r;
#pragma unroll
        for (int nt = 0; nt < 4; nt++) {
            const int col = bn + wn * 32 + nt * 8 + 2 * c;
            if (HALF_OUT) {
                __half* C = (__half*)Cv;
                *(uint32_t*)&C[(size_t)row * N + col] =
                    f22h2(acc[mt][nt][0], acc[mt][nt][1]);
                *(uint32_t*)&C[(size_t)(row + 8) * N + col] =
                    f22h2(acc[mt][nt][2], acc[mt][nt][3]);
            } else {
                float* C = (float*)Cv;
                *(float2*)&C[(size_t)row * N + col] =
                    make_float2(acc[mt][nt][0], acc[mt][nt][1]);
                *(float2*)&C[(size_t)(row + 8) * N + col] =
                    make_float2(acc[mt][nt][2], acc[mt][nt][3]);
            }
        }
    }
}

// --------------------------- attention (fp16 mma) ---------------------------
// Block = 2 x (window, head), 256 threads (4 warps per pair). Padded 64x64
// tiles; bias(-1e9) masks pads. P stays in registers (A-fragment layout).
#define AROW 40                         // halfs per smem row (80B)

__global__ void __launch_bounds__(256, 2) attn_kernel(
    const __half* __restrict__ qkv, const float* __restrict__ biasP,
    __half* __restrict__ att)
{
    __shared__ __half sq[2][64 * AROW];
    __shared__ __half sk[2][64 * AROW];
    __shared__ __half sv[2][64 * AROW];

    const int tid = threadIdx.x;
    const int sub = tid >> 7;            // which (win,head) pair
    const int st  = tid & 127;
    const int lane = tid & 31;
    const int w   = (tid >> 5) & 3;      // warp within sub
    const int pair = blockIdx.x * 2 + sub;
    const int win = pair >> 3, head = pair & 7;

    __half* q = sq[sub]; __half* k = sk[sub]; __half* v = sv[sub];

    // zero pad rows 49..63 (q,k,v): 15 rows * 4 chunks * 3 mats = 180 chunks
    for (int idx = st; idx < 180; idx += 128) {
        int m = idx / 60, rc = idx % 60;
        int row = 49 + rc / 4, ch = rc & 3;
        __half* base = (m == 0 ? q : (m == 1 ? k : v));
        *(uint4*)&base[row * AROW + ch * 8] = make_uint4(0, 0, 0, 0);
    }
    // cp.async q,k,v rows 0..48
    const __half* gbase = qkv + (size_t)win * NTOK * QKV_E + head * DH;
    for (int idx = st; idx < 588; idx += 128) {
        int m = idx / 196, rc = idx % 196;
        int row = rc >> 2, ch = rc & 3;
        __half* base = (m == 0 ? q : (m == 1 ? k : v));
        cp16(smem_u32(&base[row * AROW + ch * 8]),
             gbase + (size_t)row * QKV_E + m * DIM + ch * 8);
    }
    cp_commit();
    cp_wait<0>();
    __syncthreads();

    const int l7 = lane & 7;
    const int wr = w * 16;
    // q A-frag: rows wr + l7 (+8), halves by lane>>4
    const uint32_t qA = smem_u32(&q[(wr + l7 + ((lane >> 3) & 1) * 8) * AROW
                                    + (lane >> 4) * 8]);
    // k B-frag: per nt-pair p: rows p*16 + (lane>>4)*8 + l7, half by (lane>>3)&1
    const uint32_t kB = smem_u32(&k[((lane >> 4) * 8 + l7) * AROW
                                    + ((lane >> 3) & 1) * 8]);
    // v trans-frag: rows kt*16 + l7 + ((lane>>3)&1)*8 ; col-halves by lane>>4
    const uint32_t vB = smem_u32(&v[(l7 + ((lane >> 3) & 1) * 8) * AROW
                                    + (lane >> 4) * 8]);

    // ---- sim = q @ k^T ----
    float s[8][4];
#pragma unroll
    for (int nt = 0; nt < 8; nt++)
#pragma unroll
        for (int i = 0; i < 4; i++) s[nt][i] = 0.f;

#pragma unroll
    for (int kt = 0; kt < 2; kt++) {
        uint32_t a0, a1, a2, a3;
        ldsm4(a0, a1, a2, a3, qA + kt * 16 * 2);   // +16 halfs = 32B
#pragma unroll
        for (int p = 0; p < 4; p++) {
            uint32_t b0, b1, b2, b3;
            ldsm4(b0, b1, b2, b3, kB + p * 16 * AROW * 2 + kt * 32);
            mma16816(s[2 * p],     a0, a1, a2, a3, b0, b1);
            mma16816(s[2 * p + 1], a0, a1, a2, a3, b2, b3);
        }
    }

    // ---- scale + bias + softmax (rows r and r+8, cols nt*8+2c, +1) ----
    const int r = lane >> 2, c = lane & 3;
    const float* bp = biasP + head * 4096;
#pragma unroll
    for (int nt = 0; nt < 8; nt++) {
        float2 b0 = *(const float2*)&bp[(wr + r) * 64 + nt * 8 + 2 * c];
        float2 b1 = *(const float2*)&bp[(wr + r + 8) * 64 + nt * 8 + 2 * c];
        s[nt][0] = fmaf(s[nt][0], SCALE, b0.x);
        s[nt][1] = fmaf(s[nt][1], SCALE, b0.y);
        s[nt][2] = fmaf(s[nt][2], SCALE, b1.x);
        s[nt][3] = fmaf(s[nt][3], SCALE, b1.y);
    }
    float m0 = -1e30f, m1 = -1e30f;
#pragma unroll
    for (int nt = 0; nt < 8; nt++) {
        m0 = fmaxf(m0, fmaxf(s[nt][0], s[nt][1]));
        m1 = fmaxf(m1, fmaxf(s[nt][2], s[nt][3]));
    }
    m0 = fmaxf(m0, __shfl_xor_sync(0xffffffffu, m0, 1));
    m0 = fmaxf(m0, __shfl_xor_sync(0xffffffffu, m0, 2));
    m1 = fmaxf(m1, __shfl_xor_sync(0xffffffffu, m1, 1));
    m1 = fmaxf(m1, __shfl_xor_sync(0xffffffffu, m1, 2));
    float sum0 = 0.f, sum1 = 0.f;
#pragma unroll
    for (int nt = 0; nt < 8; nt++) {
        s[nt][0] = __expf(s[nt][0] - m0);
        s[nt][1] = __expf(s[nt][1] - m0);
        s[nt][2] = __expf(s[nt][2] - m1);
        s[nt][3] = __expf(s[nt][3] - m1);
        sum0 += s[nt][0] + s[nt][1];
        sum1 += s[nt][2] + s[nt][3];
    }
    sum0 += __shfl_xor_sync(0xffffffffu, sum0, 1);
    sum0 += __shfl_xor_sync(0xffffffffu, sum0, 2);
    sum1 += __shfl_xor_sync(0xffffffffu, sum1, 1);
    sum1 += __shfl_xor_sync(0xffffffffu, sum1, 2);
    const float inv0 = 1.f / sum0, inv1 = 1.f / sum1;

    // ---- P fragments (A layout), unnormalized; fold inv at store ----
    uint32_t pf[4][4];
#pragma unroll
    for (int kt = 0; kt < 4; kt++) {
        pf[kt][0] = f22h2(s[2 * kt][0],     s[2 * kt][1]);
        pf[kt][1] = f22h2(s[2 * kt][2],     s[2 * kt][3]);
        pf[kt][2] = f22h2(s[2 * kt + 1][0], s[2 * kt + 1][1]);
        pf[kt][3] = f22h2(s[2 * kt + 1][2], s[2 * kt + 1][3]);
    }

    // ---- out = P @ V ----
    float o[4][4];
#pragma unroll
    for (int nb = 0; nb < 4; nb++)
#pragma unroll
        for (int i = 0; i < 4; i++) o[nb][i] = 0.f;
#pragma unroll
    for (int kt = 0; kt < 4; kt++) {
#pragma unroll
        for (int p = 0; p < 2; p++) {    // nb pairs (0,1) and (2,3)
            uint32_t b0, b1, b2, b3;
            ldsm4t(b0, b1, b2, b3, vB + kt * 16 * AROW * 2 + p * 32);
            mma16816(o[2 * p],     pf[kt][0], pf[kt][1], pf[kt][2], pf[kt][3], b0, b1);
            mma16816(o[2 * p + 1], pf[kt][0], pf[kt][1], pf[kt][2], pf[kt][3], b2, b3);
        }
    }

    // ---- store att (fp16), rows wr+r and wr+r+8 if real ----
    const int row0 = wr + r, row1 = wr + r + 8;
#pragma unroll
    for (int nb = 0; nb < 4; nb++) {
        const int col = head * DH + nb * 8 + 2 * c;
        if (row0 < NTOK)
            *(uint32_t*)&att[((size_t)win * NTOK + row0) * DIM + col] =
                f22h2(o[nb][0] * inv0, o[nb][1] * inv0);
        if (row1 < NTOK)
            *(uint32_t*)&att[((size_t)win * NTOK + row1) * DIM + col] =
                f22h2(o[nb][2] * inv1, o[nb][3] * inv1);
    }
}

// ------------------------------ prep kernels --------------------------------
__global__ void cvt_h_kernel(const float4* __restrict__ in,
                             uint2* __restrict__ out, int n4)
{
    int i = blockIdx.x * 256 + threadIdx.x;
    if (i < n4) {
        float4 vx = in[i];
        out[i] = make_uint2(f22h2(vx.x, vx.y), f22h2(vx.z, vx.w));
    }
}

__global__ void bias_pad_kernel(const float* __restrict__ rel_emb,
                                const int* __restrict__ rel_idx,
                                float* __restrict__ biasP)
{
    int e = blockIdx.x * 256 + threadIdx.x;   // 8*64*64
    if (e < HEADS * 64 * 64) {
        int h = e >> 12, rc = e & 4095, rr = rc >> 6, cc = rc & 63;
        biasP[e] = (rr < NTOK && cc < NTOK)
                 ? rel_emb[rel_idx[rr * NTOK + cc] * HEADS + h] : -1e9f;
    }
}

// ----------------------------------------------------------------------------
extern "C" void kernel_launch(void* const* d_in, const int* in_sizes, int n_in,
                              void* d_out, int out_size)
{
    const float* x       = (const float*)d_in[0];
    const float* w_qkv   = (const float*)d_in[1];
    const float* w_out   = (const float*)d_in[2];
    const float* rel_emb = (const float*)d_in[3];
    const int*   rel_idx = (const int*)d_in[4];
    float* out = (float*)d_out;

    __half *x16, *wq16, *wo16, *qkv, *att;
    float* biasP;
    cudaGetSymbolAddress((void**)&x16,  g_x16);
    cudaGetSymbolAddress((void**)&wq16, g_wq16);
    cudaGetSymbolAddress((void**)&wo16, g_wo16);
    cudaGetSymbolAddress((void**)&qkv,  g_qkv);
    cudaGetSymbolAddress((void**)&att,  g_att);
    cudaGetSymbolAddress((void**)&biasP, g_biasP);

    cudaFuncSetAttribute(gemm_h_kernel<1>,
                         cudaFuncAttributeMaxDynamicSharedMemorySize, GSMEM);
    cudaFuncSetAttribute(gemm_h_kernel<0>,
                         cudaFuncAttributeMaxDynamicSharedMemorySize, GSMEM);

    // fp16 conversions
    int n4x = TTOT * DIM / 4;
    cvt_h_kernel<<<(n4x + 255) / 256, 256>>>((const float4*)x, (uint2*)x16, n4x);
    cvt_h_kernel<<<(QKV_E * DIM / 4 + 255) / 256, 256>>>(
        (const float4*)w_qkv, (uint2*)wq16, QKV_E * DIM / 4);
    cvt_h_kernel<<<(DIM * DIM / 4 + 255) / 256, 256>>>(
        (const float4*)w_out, (uint2*)wo16, DIM * DIM / 4);
    bias_pad_kernel<<<(HEADS * 64 * 64 + 255) / 256, 256>>>(rel_emb, rel_idx, biasP);

    // 1) qkv = x @ w_qkv^T  (fp16 in, fp16 out)
    gemm_h_kernel<1><<<dim3(QKV_E / 128, TTOT / 128), 256, GSMEM>>>(
        x16, wq16, qkv, TTOT, QKV_E, DIM);

    // 2) windowed attention (tensor cores, P in registers)
    attn_kernel<<<WINS * HEADS / 2, 256>>>(qkv, biasP, att);

    // 3) out = att @ w_out^T (fp16 in, fp32 out)
    gemm_h_kernel<0><<<dim3(DIM / 128, TTOT / 128), 256, GSMEM>>>(
        att, wo16, out, TTOT, DIM, DIM);
}